// round 2
// baseline (speedup 1.0000x reference)
#include <cuda_runtime.h>
#include <cuda_bf16.h>

// ---------------- scratch (static device memory; no allocation) ----------------
__device__ float g_zn[65536ull * 128];   // layernormed z
__device__ float g_P [65536ull * 512];   // q|k|v|g projections
__device__ float g_GA[65536ull * 128];   // gate * attn_out
__device__ float g_Wcat[512 * 128];      // packed q_w,k_w,v_w,g_w
__device__ float g_Bcat[512];            // packed biases

typedef unsigned long long u64;

// ---------------- f32x2 packed-FMA helpers (sm_103a) ----------------
__device__ __forceinline__ u64 frep2(float x) {
    u64 r; asm("mov.b64 %0, {%1, %1};" : "=l"(r) : "f"(x)); return r;
}
__device__ __forceinline__ void ffma2(u64& d, u64 a, u64 b) {
    asm("fma.rn.f32x2 %0, %1, %2, %0;" : "+l"(d) : "l"(a), "l"(b));
}
__device__ __forceinline__ float2 funpk(u64 d) {
    float2 f; asm("mov.b64 {%0, %1}, %2;" : "=f"(f.x), "=f"(f.y) : "l"(d)); return f;
}

// ---------------- K0: pack weights ----------------
__global__ void pack_kernel(const float* __restrict__ qw, const float* __restrict__ kw,
                            const float* __restrict__ vw, const float* __restrict__ gw,
                            const float* __restrict__ qb, const float* __restrict__ kb,
                            const float* __restrict__ vb, const float* __restrict__ gb) {
    int idx = blockIdx.x * 256 + threadIdx.x;           // 0 .. 65535
    int row = idx >> 7, col = idx & 127;
    const float* w = (row < 128) ? qw : (row < 256) ? kw : (row < 384) ? vw : gw;
    g_Wcat[idx] = w[(row & 127) * 128 + col];
    if (idx < 512) {
        const float* b = (idx < 128) ? qb : (idx < 256) ? kb : (idx < 384) ? vb : gb;
        g_Bcat[idx] = b[idx & 127];
    }
}

// ---------------- K1: LayerNorm over last dim (128) ----------------
__global__ void ln_kernel(const float* __restrict__ z,
                          const float* __restrict__ lw,
                          const float* __restrict__ lb) {
    int warp = threadIdx.x >> 5, lane = threadIdx.x & 31;
    int t = blockIdx.x * 8 + warp;
    const float4* zp = (const float4*)(z + (size_t)t * 128);
    float4 v = zp[lane];
    float s = v.x + v.y + v.z + v.w;
    float q = v.x * v.x + v.y * v.y + v.z * v.z + v.w * v.w;
    #pragma unroll
    for (int o = 16; o; o >>= 1) {
        s += __shfl_xor_sync(0xFFFFFFFFu, s, o);
        q += __shfl_xor_sync(0xFFFFFFFFu, q, o);
    }
    float mu  = s * (1.0f / 128.0f);
    float var = q * (1.0f / 128.0f) - mu * mu;
    float rs  = rsqrtf(var + 1e-5f);
    float4 w4 = ((const float4*)lw)[lane];
    float4 b4 = ((const float4*)lb)[lane];
    float4 o4;
    o4.x = (v.x - mu) * rs * w4.x + b4.x;
    o4.y = (v.y - mu) * rs * w4.y + b4.y;
    o4.z = (v.z - mu) * rs * w4.z + b4.z;
    o4.w = (v.w - mu) * rs * w4.w + b4.w;
    ((float4*)(g_zn + (size_t)t * 128))[lane] = o4;
}

// ---------------- K2/K4: SGEMM  C[m][n] = sum_k A[m][k]*Bw[n][k] + bias[n] ----------------
// K fixed = 128. BM=BN=128, BK=16, 256 threads, 8x8 thread tile via f32x2 FMA.
// EPI==1: plain write.  EPI==2: multiply row by (float)mask[row].
template<int EPI>
__global__ void __launch_bounds__(256) sgemm_k128(const float* __restrict__ A,
                                                  const float* __restrict__ Bw,
                                                  const float* __restrict__ bias,
                                                  const int*   __restrict__ mask,
                                                  float* __restrict__ C, int Ntot) {
    __shared__ float As[16 * 132];
    __shared__ float Bs[16 * 132];
    int tid = threadIdx.x;
    int tx = tid & 15, ty = tid >> 4;
    int bm0 = blockIdx.x * 128, bn0 = blockIdx.y * 128;

    u64 acc[4][8];
    #pragma unroll
    for (int p = 0; p < 4; p++)
        #pragma unroll
        for (int j = 0; j < 8; j++) acc[p][j] = 0ull;

    #pragma unroll 1
    for (int kt = 0; kt < 8; kt++) {
        __syncthreads();
        #pragma unroll
        for (int i = 0; i < 2; i++) {
            int idx = tid + i * 256;
            int row = idx >> 2, seg = idx & 3;
            float4 av = *(const float4*)(A  + (size_t)(bm0 + row) * 128 + kt * 16 + seg * 4);
            float4 bv = *(const float4*)(Bw + (size_t)(bn0 + row) * 128 + kt * 16 + seg * 4);
            As[(seg * 4 + 0) * 132 + row] = av.x;
            As[(seg * 4 + 1) * 132 + row] = av.y;
            As[(seg * 4 + 2) * 132 + row] = av.z;
            As[(seg * 4 + 3) * 132 + row] = av.w;
            Bs[(seg * 4 + 0) * 132 + row] = bv.x;
            Bs[(seg * 4 + 1) * 132 + row] = bv.y;
            Bs[(seg * 4 + 2) * 132 + row] = bv.z;
            Bs[(seg * 4 + 3) * 132 + row] = bv.w;
        }
        __syncthreads();
        #pragma unroll
        for (int kk = 0; kk < 16; kk++) {
            u64 a2[4];
            #pragma unroll
            for (int p = 0; p < 4; p++)
                a2[p] = *(const u64*)&As[kk * 132 + ty * 8 + 2 * p];
            float4 b0 = *(const float4*)&Bs[kk * 132 + tx * 8];
            float4 b1 = *(const float4*)&Bs[kk * 132 + tx * 8 + 4];
            u64 b2[8];
            b2[0] = frep2(b0.x); b2[1] = frep2(b0.y); b2[2] = frep2(b0.z); b2[3] = frep2(b0.w);
            b2[4] = frep2(b1.x); b2[5] = frep2(b1.y); b2[6] = frep2(b1.z); b2[7] = frep2(b1.w);
            #pragma unroll
            for (int p = 0; p < 4; p++)
                #pragma unroll
                for (int j = 0; j < 8; j++) ffma2(acc[p][j], a2[p], b2[j]);
        }
    }

    float bb[8];
    #pragma unroll
    for (int j = 0; j < 8; j++) bb[j] = bias[bn0 + tx * 8 + j];

    #pragma unroll
    for (int p = 0; p < 4; p++) {
        float2 uv[8];
        #pragma unroll
        for (int j = 0; j < 8; j++) uv[j] = funpk(acc[p][j]);
        #pragma unroll
        for (int s2 = 0; s2 < 2; s2++) {
            int row = bm0 + ty * 8 + 2 * p + s2;
            float mf = 1.0f;
            if (EPI == 2) mf = (float)mask[row];
            float4 o0, o1;
            o0.x = ((s2 ? uv[0].y : uv[0].x) + bb[0]) * mf;
            o0.y = ((s2 ? uv[1].y : uv[1].x) + bb[1]) * mf;
            o0.z = ((s2 ? uv[2].y : uv[2].x) + bb[2]) * mf;
            o0.w = ((s2 ? uv[3].y : uv[3].x) + bb[3]) * mf;
            o1.x = ((s2 ? uv[4].y : uv[4].x) + bb[4]) * mf;
            o1.y = ((s2 ? uv[5].y : uv[5].x) + bb[5]) * mf;
            o1.z = ((s2 ? uv[6].y : uv[6].x) + bb[6]) * mf;
            o1.w = ((s2 ? uv[7].y : uv[7].x) + bb[7]) * mf;
            float* Cr = C + (size_t)row * Ntot + bn0 + tx * 8;
            *(float4*)Cr = o0;
            *((float4*)Cr + 1) = o1;
        }
    }
}

// ---------------- K3: per-(row, head) linear attention ----------------
// grid (256 rows, 4 heads), 256 threads, dynamic smem 188928 bytes.
__global__ void __launch_bounds__(256) attn_kernel(const int*   __restrict__ pm,
                                                   const float* __restrict__ qfw,
                                                   const float* __restrict__ qfb,
                                                   const float* __restrict__ kfw,
                                                   const float* __restrict__ kfb) {
    extern __shared__ float sm[];
    float* s_kf  = sm;            // [256][66]
    float* s_vm  = sm + 16896;    // [256][36]
    float* s_kvp = sm + 26112;    // [8][2048]
    float* s_kv  = sm + 42496;    // [64*32]
    float* s_ks  = sm + 44544;    // [64]
    float* s_ksp = sm + 44608;    // [8][64]
    float* s_kfw = sm + 45120;    // [1024]
    float* s_kfb = sm + 46144;    // [32]
    float* s_qfw = sm + 46176;    // [1024]
    float* s_qfb = sm + 47200;    // [32]

    int tid = threadIdx.x;
    int r = blockIdx.x, h = blockIdx.y;

    for (int i = tid; i < 1024; i += 256) { s_kfw[i] = kfw[i]; s_qfw[i] = qfw[i]; }
    if (tid < 32) { s_kfb[tid] = kfb[tid]; s_qfb[tid] = qfb[tid]; }

    int n = tid;
    int t = r * 256 + n;
    float maskf = (float)pm[t];
    const float* Pt = g_P + (size_t)t * 512 + h * 32;

    __syncthreads();

    // ---- step A: kf = feature(k_h)*mask, vm = v_h*mask ----
    {
        float kvec[32];
        #pragma unroll
        for (int i = 0; i < 8; i++) {
            float4 v4 = *(const float4*)(Pt + 128 + i * 4);
            kvec[4 * i] = v4.x; kvec[4 * i + 1] = v4.y; kvec[4 * i + 2] = v4.z; kvec[4 * i + 3] = v4.w;
        }
        #pragma unroll
        for (int jg = 0; jg < 4; jg++) {
            float a8[8];
            #pragma unroll
            for (int jj = 0; jj < 8; jj++) a8[jj] = s_kfb[jg * 8 + jj];
            #pragma unroll
            for (int d = 0; d < 32; d++)
                #pragma unroll
                for (int jj = 0; jj < 8; jj++) a8[jj] += kvec[d] * s_kfw[(jg * 8 + jj) * 32 + d];
            #pragma unroll
            for (int jj = 0; jj < 8; jj++) {
                float m = fminf(8.0f, fmaxf(-8.0f, a8[jj]));
                float e = __expf(m);
                s_kf[n * 66 + jg * 8 + jj]      = e * maskf;
                s_kf[n * 66 + 32 + jg * 8 + jj] = (maskf / e);   // exp(-m)*mask
            }
        }
        #pragma unroll
        for (int i = 0; i < 8; i++) {
            float4 v4 = *(const float4*)(Pt + 256 + i * 4);
            s_vm[n * 36 + 4 * i]     = v4.x * maskf;
            s_vm[n * 36 + 4 * i + 1] = v4.y * maskf;
            s_vm[n * 36 + 4 * i + 2] = v4.z * maskf;
            s_vm[n * 36 + 4 * i + 3] = v4.w * maskf;
        }
    }
    __syncthreads();

    // ---- step B: per-warp partial kv[64][32] and ksum[64] ----
    {
        int lane = tid & 31, w = tid >> 5;
        int fy = lane >> 2, dx = lane & 3;        // f base = fy*8, d base = dx*8
        float acc[8][8];
        float ks[8];
        #pragma unroll
        for (int fi = 0; fi < 8; fi++) {
            ks[fi] = 0.0f;
            #pragma unroll
            for (int di = 0; di < 8; di++) acc[fi][di] = 0.0f;
        }
        #pragma unroll 2
        for (int i = 0; i < 32; i++) {
            int nn = w * 32 + i;
            float kfv[8];
            #pragma unroll
            for (int q2 = 0; q2 < 4; q2++) {
                float2 v2 = *(const float2*)&s_kf[nn * 66 + fy * 8 + q2 * 2];
                kfv[q2 * 2] = v2.x; kfv[q2 * 2 + 1] = v2.y;
            }
            float vmv[8];
            float4 a4 = *(const float4*)&s_vm[nn * 36 + dx * 8];
            float4 b4 = *(const float4*)&s_vm[nn * 36 + dx * 8 + 4];
            vmv[0] = a4.x; vmv[1] = a4.y; vmv[2] = a4.z; vmv[3] = a4.w;
            vmv[4] = b4.x; vmv[5] = b4.y; vmv[6] = b4.z; vmv[7] = b4.w;
            #pragma unroll
            for (int fi = 0; fi < 8; fi++)
                #pragma unroll
                for (int di = 0; di < 8; di++) acc[fi][di] += kfv[fi] * vmv[di];
            if (dx == 0) {
                #pragma unroll
                for (int fi = 0; fi < 8; fi++) ks[fi] += kfv[fi];
            }
        }
        #pragma unroll
        for (int fi = 0; fi < 8; fi++) {
            float4 o0 = make_float4(acc[fi][0], acc[fi][1], acc[fi][2], acc[fi][3]);
            float4 o1 = make_float4(acc[fi][4], acc[fi][5], acc[fi][6], acc[fi][7]);
            *(float4*)&s_kvp[w * 2048 + (fy * 8 + fi) * 32 + dx * 8]     = o0;
            *(float4*)&s_kvp[w * 2048 + (fy * 8 + fi) * 32 + dx * 8 + 4] = o1;
        }
        if (dx == 0) {
            #pragma unroll
            for (int fi = 0; fi < 8; fi++) s_ksp[w * 64 + fy * 8 + fi] = ks[fi];
        }
    }
    __syncthreads();

    // ---- reduce partials -> s_kv, s_ks ----
    {
        int e = tid * 8;
        float4 r0 = make_float4(0, 0, 0, 0), r1 = make_float4(0, 0, 0, 0);
        #pragma unroll
        for (int w2 = 0; w2 < 8; w2++) {
            float4 p0 = *(const float4*)&s_kvp[w2 * 2048 + e];
            float4 p1 = *(const float4*)&s_kvp[w2 * 2048 + e + 4];
            r0.x += p0.x; r0.y += p0.y; r0.z += p0.z; r0.w += p0.w;
            r1.x += p1.x; r1.y += p1.y; r1.z += p1.z; r1.w += p1.w;
        }
        *(float4*)&s_kv[e]     = r0;
        *(float4*)&s_kv[e + 4] = r1;
        if (tid < 64) {
            float s = 0.0f;
            #pragma unroll
            for (int w2 = 0; w2 < 8; w2++) s += s_ksp[w2 * 64 + tid];
            s_ks[tid] = s;
        }
    }
    __syncthreads();

    // ---- step C: qf features, num = qf @ kv, denom, gate, write GA ----
    {
        float qf[64];
        {
            float qvec[32];
            #pragma unroll
            for (int i = 0; i < 8; i++) {
                float4 v4 = *(const float4*)(Pt + 0 + i * 4);
                qvec[4 * i] = v4.x; qvec[4 * i + 1] = v4.y; qvec[4 * i + 2] = v4.z; qvec[4 * i + 3] = v4.w;
            }
            #pragma unroll
            for (int jg = 0; jg < 4; jg++) {
                float a8[8];
                #pragma unroll
                for (int jj = 0; jj < 8; jj++) a8[jj] = s_qfb[jg * 8 + jj];
                #pragma unroll
                for (int d = 0; d < 32; d++)
                    #pragma unroll
                    for (int jj = 0; jj < 8; jj++) a8[jj] += qvec[d] * s_qfw[(jg * 8 + jj) * 32 + d];
                #pragma unroll
                for (int jj = 0; jj < 8; jj++) {
                    float m = fminf(8.0f, fmaxf(-8.0f, a8[jj]));
                    float e = __expf(m);
                    qf[jg * 8 + jj]      = e;
                    qf[32 + jg * 8 + jj] = 1.0f / e;
                }
            }
        }
        float num[32];
        #pragma unroll
        for (int d = 0; d < 32; d++) num[d] = 0.0f;
        float den = 0.0f;
        #pragma unroll 4
        for (int f = 0; f < 64; f++) {
            float qv = qf[f];
            den += qv * s_ks[f];
            #pragma unroll
            for (int d = 0; d < 32; d++) num[d] += qv * s_kv[f * 32 + d];
        }
        den = fmaxf(den, 1e-6f);
        float inv = 1.0f / den;
        float* GAt = g_GA + (size_t)t * 128 + h * 32;
        #pragma unroll
        for (int i = 0; i < 8; i++) {
            float4 g4 = *(const float4*)(Pt + 384 + i * 4);
            float4 o4;
            o4.x = (1.0f / (1.0f + __expf(-g4.x))) * num[4 * i]     * inv;
            o4.y = (1.0f / (1.0f + __expf(-g4.y))) * num[4 * i + 1] * inv;
            o4.z = (1.0f / (1.0f + __expf(-g4.z))) * num[4 * i + 2] * inv;
            o4.w = (1.0f / (1.0f + __expf(-g4.w))) * num[4 * i + 3] * inv;
            *(float4*)(GAt + 4 * i) = o4;
        }
    }
}

// ---------------- launcher ----------------
extern "C" void kernel_launch(void* const* d_in, const int* in_sizes, int n_in,
                              void* d_out, int out_size) {
    const float* z    = (const float*)d_in[0];
    const int*   pm   = (const int*)  d_in[1];
    const float* lnw  = (const float*)d_in[2];
    const float* lnb  = (const float*)d_in[3];
    const float* qw   = (const float*)d_in[4];
    const float* qb   = (const float*)d_in[5];
    const float* kw   = (const float*)d_in[6];
    const float* kb   = (const float*)d_in[7];
    const float* vw   = (const float*)d_in[8];
    const float* vb   = (const float*)d_in[9];
    const float* qfw  = (const float*)d_in[10];
    const float* qfb  = (const float*)d_in[11];
    const float* kfw  = (const float*)d_in[12];
    const float* kfb  = (const float*)d_in[13];
    const float* gw   = (const float*)d_in[14];
    const float* gb   = (const float*)d_in[15];
    const float* ow   = (const float*)d_in[16];
    const float* ob   = (const float*)d_in[17];
    float* out = (float*)d_out;

    static int smem_set = 0;
    if (!smem_set) {
        cudaFuncSetAttribute(attn_kernel, cudaFuncAttributeMaxDynamicSharedMemorySize, 188928);
        smem_set = 1;
    }

    float* Wcat; cudaGetSymbolAddress((void**)&Wcat, g_Wcat);
    float* Bcat; cudaGetSymbolAddress((void**)&Bcat, g_Bcat);
    float* Zn;   cudaGetSymbolAddress((void**)&Zn,   g_zn);
    float* Pp;   cudaGetSymbolAddress((void**)&Pp,   g_P);
    float* GA;   cudaGetSymbolAddress((void**)&GA,   g_GA);

    pack_kernel<<<256, 256>>>(qw, kw, vw, gw, qb, kb, vb, gb);
    ln_kernel<<<8192, 256>>>(z, lnw, lnb);
    sgemm_k128<1><<<dim3(512, 4), 256>>>(Zn, Wcat, Bcat, nullptr, Pp, 512);
    attn_kernel<<<dim3(256, 4), 256, 188928>>>(pm, qfw, qfb, kfw, kfb);
    sgemm_k128<2><<<dim3(512, 1), 256>>>(GA, ow, ob, pm, out, 128);
}

// round 3
// speedup vs baseline: 1.0646x; 1.0646x over previous
#include <cuda_runtime.h>
#include <cuda_bf16.h>

// ---------------- scratch (static device memory; no allocation) ----------------
__device__ float g_zn[65536ull * 128];   // layernormed z
__device__ float g_P [65536ull * 512];   // q|k|v|g projections
__device__ float g_GA[65536ull * 128];   // gate * attn_out
__device__ float g_Wcat[512 * 128];      // packed q_w,k_w,v_w,g_w
__device__ float g_Bcat[512];            // packed biases

typedef unsigned long long u64;

// ---------------- f32x2 packed-FMA helpers (sm_103a) ----------------
__device__ __forceinline__ u64 frep2(float x) {
    u64 r; asm("mov.b64 %0, {%1, %1};" : "=l"(r) : "f"(x)); return r;
}
__device__ __forceinline__ void ffma2(u64& d, u64 a, u64 b) {
    asm("fma.rn.f32x2 %0, %1, %2, %0;" : "+l"(d) : "l"(a), "l"(b));
}
__device__ __forceinline__ float2 funpk(u64 d) {
    float2 f; asm("mov.b64 {%0, %1}, %2;" : "=f"(f.x), "=f"(f.y) : "l"(d)); return f;
}

// ---------------- K0: pack weights ----------------
__global__ void pack_kernel(const float* __restrict__ qw, const float* __restrict__ kw,
                            const float* __restrict__ vw, const float* __restrict__ gw,
                            const float* __restrict__ qb, const float* __restrict__ kb,
                            const float* __restrict__ vb, const float* __restrict__ gb) {
    int idx = blockIdx.x * 256 + threadIdx.x;           // 0 .. 65535
    int row = idx >> 7, col = idx & 127;
    const float* w = (row < 128) ? qw : (row < 256) ? kw : (row < 384) ? vw : gw;
    g_Wcat[idx] = w[(row & 127) * 128 + col];
    if (idx < 512) {
        const float* b = (idx < 128) ? qb : (idx < 256) ? kb : (idx < 384) ? vb : gb;
        g_Bcat[idx] = b[idx & 127];
    }
}

// ---------------- K1: LayerNorm over last dim (128) ----------------
__global__ void ln_kernel(const float* __restrict__ z,
                          const float* __restrict__ lw,
                          const float* __restrict__ lb) {
    int warp = threadIdx.x >> 5, lane = threadIdx.x & 31;
    int t = blockIdx.x * 8 + warp;
    const float4* zp = (const float4*)(z + (size_t)t * 128);
    float4 v = zp[lane];
    float s = v.x + v.y + v.z + v.w;
    float q = v.x * v.x + v.y * v.y + v.z * v.z + v.w * v.w;
    #pragma unroll
    for (int o = 16; o; o >>= 1) {
        s += __shfl_xor_sync(0xFFFFFFFFu, s, o);
        q += __shfl_xor_sync(0xFFFFFFFFu, q, o);
    }
    float mu  = s * (1.0f / 128.0f);
    float var = q * (1.0f / 128.0f) - mu * mu;
    float rs  = rsqrtf(var + 1e-5f);
    float4 w4 = ((const float4*)lw)[lane];
    float4 b4 = ((const float4*)lb)[lane];
    float4 o4;
    o4.x = (v.x - mu) * rs * w4.x + b4.x;
    o4.y = (v.y - mu) * rs * w4.y + b4.y;
    o4.z = (v.z - mu) * rs * w4.z + b4.z;
    o4.w = (v.w - mu) * rs * w4.w + b4.w;
    ((float4*)(g_zn + (size_t)t * 128))[lane] = o4;
}

// ---------------- K2/K4: SGEMM  C[m][n] = sum_k A[m][k]*Bw[n][k] + bias[n] ----------------
// K fixed = 128. BM=BN=128, BK=16, 256 threads, 8x8 thread tile via f32x2 FMA.
// B stored duplicated in smem: chunk t (n-cols t*8..t*8+7) at stride-20 floats,
// each value as an (v,v) pair -> inner loop loads u64 operands directly.
// EPI==1: plain write.  EPI==2: multiply row by (float)mask[row].
template<int EPI>
__global__ void __launch_bounds__(256) sgemm_k128(const float* __restrict__ A,
                                                  const float* __restrict__ Bw,
                                                  const float* __restrict__ bias,
                                                  const int*   __restrict__ mask,
                                                  float* __restrict__ C, int Ntot) {
    __shared__ float As [16 * 132];
    __shared__ float Bs2[16 * 320];
    int tid = threadIdx.x;
    int tx = tid & 15, ty = tid >> 4;
    int bm0 = blockIdx.x * 128, bn0 = blockIdx.y * 128;

    u64 acc[4][8];
    #pragma unroll
    for (int p = 0; p < 4; p++)
        #pragma unroll
        for (int j = 0; j < 8; j++) acc[p][j] = 0ull;

    #pragma unroll 1
    for (int kt = 0; kt < 8; kt++) {
        __syncthreads();
        #pragma unroll
        for (int i = 0; i < 2; i++) {
            int idx = tid + i * 256;
            int row = idx >> 2, seg = idx & 3;
            float4 av = *(const float4*)(A  + (size_t)(bm0 + row) * 128 + kt * 16 + seg * 4);
            float4 bv = *(const float4*)(Bw + (size_t)(bn0 + row) * 128 + kt * 16 + seg * 4);
            As[(seg * 4 + 0) * 132 + row] = av.x;
            As[(seg * 4 + 1) * 132 + row] = av.y;
            As[(seg * 4 + 2) * 132 + row] = av.z;
            As[(seg * 4 + 3) * 132 + row] = av.w;
            int bt = row >> 3, bj = row & 7;
            float bvals[4] = {bv.x, bv.y, bv.z, bv.w};
            #pragma unroll
            for (int c = 0; c < 4; c++) {
                *(float2*)&Bs2[(seg * 4 + c) * 320 + bt * 20 + bj * 2] =
                    make_float2(bvals[c], bvals[c]);
            }
        }
        __syncthreads();
        #pragma unroll
        for (int kk = 0; kk < 16; kk++) {
            ulonglong2 A0 = *(const ulonglong2*)&As[kk * 132 + ty * 8];
            ulonglong2 A1 = *(const ulonglong2*)&As[kk * 132 + ty * 8 + 4];
            u64 a2[4] = {A0.x, A0.y, A1.x, A1.y};
            const ulonglong2* bp = (const ulonglong2*)&Bs2[kk * 320 + tx * 20];
            ulonglong2 B0 = bp[0], B1 = bp[1], B2 = bp[2], B3 = bp[3];
            u64 b2[8] = {B0.x, B0.y, B1.x, B1.y, B2.x, B2.y, B3.x, B3.y};
            #pragma unroll
            for (int p = 0; p < 4; p++)
                #pragma unroll
                for (int j = 0; j < 8; j++) ffma2(acc[p][j], a2[p], b2[j]);
        }
    }

    float bb[8];
    #pragma unroll
    for (int j = 0; j < 8; j++) bb[j] = bias[bn0 + tx * 8 + j];

    #pragma unroll
    for (int p = 0; p < 4; p++) {
        float2 uv[8];
        #pragma unroll
        for (int j = 0; j < 8; j++) uv[j] = funpk(acc[p][j]);
        #pragma unroll
        for (int s2 = 0; s2 < 2; s2++) {
            int row = bm0 + ty * 8 + 2 * p + s2;
            float mf = 1.0f;
            if (EPI == 2) mf = (float)mask[row];
            float4 o0, o1;
            o0.x = ((s2 ? uv[0].y : uv[0].x) + bb[0]) * mf;
            o0.y = ((s2 ? uv[1].y : uv[1].x) + bb[1]) * mf;
            o0.z = ((s2 ? uv[2].y : uv[2].x) + bb[2]) * mf;
            o0.w = ((s2 ? uv[3].y : uv[3].x) + bb[3]) * mf;
            o1.x = ((s2 ? uv[4].y : uv[4].x) + bb[4]) * mf;
            o1.y = ((s2 ? uv[5].y : uv[5].x) + bb[5]) * mf;
            o1.z = ((s2 ? uv[6].y : uv[6].x) + bb[6]) * mf;
            o1.w = ((s2 ? uv[7].y : uv[7].x) + bb[7]) * mf;
            float* Cr = C + (size_t)row * Ntot + bn0 + tx * 8;
            *(float4*)Cr = o0;
            *((float4*)Cr + 1) = o1;
        }
    }
}

// ---------------- K3: per-(row, head) linear attention ----------------
// grid (256 rows, 4 heads), 256 threads, dynamic smem 106624 bytes -> 2 CTAs/SM.
// smem layout (floats):
//   s_kf  @0      [256][66] = 16896   (later aliased: s_kvp [8][2048]=16384)
//   s_vm  @16896  [256][34] = 8704    (later aliased: s_ksp[512], s_kv[2048], s_ks[64])
//   s_w   @25600  [1056]  kf weights+bias, then reloaded with qf weights+bias
__global__ void __launch_bounds__(256, 2) attn_kernel(const int*   __restrict__ pm,
                                                      const float* __restrict__ qfw,
                                                      const float* __restrict__ qfb,
                                                      const float* __restrict__ kfw,
                                                      const float* __restrict__ kfb) {
    extern __shared__ float sm[];
    float* s_kf  = sm;                  // [256][66]
    float* s_vm  = sm + 16896;          // [256][34]
    float* s_kvp = sm;                  // alias [8][2048]
    float* s_ksp = sm + 16896;          // alias [8][64]
    float* s_kv  = sm + 16896 + 512;    // [2048]
    float* s_ks  = sm + 16896 + 2560;   // [64]
    float* s_w   = sm + 25600;          // [1056]

    int tid = threadIdx.x;
    int r = blockIdx.x, h = blockIdx.y;

    for (int i = tid; i < 1024; i += 256) s_w[i] = kfw[i];
    if (tid < 32) s_w[1024 + tid] = kfb[tid];

    int n = tid;
    int t = r * 256 + n;
    float maskf = (float)pm[t];
    const float* Pt = g_P + (size_t)t * 512 + h * 32;

    __syncthreads();

    // ---- step A: kf = feature(k_h)*mask, vm = v_h*mask ----
    {
        float kvec[32];
        #pragma unroll
        for (int i = 0; i < 8; i++) {
            float4 v4 = *(const float4*)(Pt + 128 + i * 4);
            kvec[4 * i] = v4.x; kvec[4 * i + 1] = v4.y; kvec[4 * i + 2] = v4.z; kvec[4 * i + 3] = v4.w;
        }
        #pragma unroll
        for (int jg = 0; jg < 4; jg++) {
            float a8[8];
            #pragma unroll
            for (int jj = 0; jj < 8; jj++) a8[jj] = s_w[1024 + jg * 8 + jj];
            #pragma unroll
            for (int d = 0; d < 32; d++) {
                float kd = kvec[d];
                #pragma unroll
                for (int jj = 0; jj < 8; jj++) a8[jj] += kd * s_w[(jg * 8 + jj) * 32 + d];
            }
            #pragma unroll
            for (int jj = 0; jj < 8; jj++) {
                float m = fminf(8.0f, fmaxf(-8.0f, a8[jj]));
                s_kf[n * 66 + jg * 8 + jj]      = __expf(m)  * maskf;
                s_kf[n * 66 + 32 + jg * 8 + jj] = __expf(-m) * maskf;
            }
        }
        #pragma unroll
        for (int i = 0; i < 8; i++) {
            float4 v4 = *(const float4*)(Pt + 256 + i * 4);
            *(float2*)&s_vm[n * 34 + 4 * i]     = make_float2(v4.x * maskf, v4.y * maskf);
            *(float2*)&s_vm[n * 34 + 4 * i + 2] = make_float2(v4.z * maskf, v4.w * maskf);
        }
    }
    __syncthreads();

    // ---- step B: per-warp partial kv[64][32] (f32x2) + ksum, in registers ----
    int lane = tid & 31, w = tid >> 5;
    int fy = lane >> 2, dx = lane & 3;          // f base = fy*8, d base = dx*8
    u64 acc2[8][4];
    float ks[8];
    #pragma unroll
    for (int fi = 0; fi < 8; fi++) {
        ks[fi] = 0.0f;
        #pragma unroll
        for (int q = 0; q < 4; q++) acc2[fi][q] = 0ull;
    }
    #pragma unroll 2
    for (int i = 0; i < 32; i++) {
        int nn = w * 32 + i;
        const float* kfp = &s_kf[nn * 66 + fy * 8];
        float kfv[8];
        #pragma unroll
        for (int q = 0; q < 4; q++) {
            float2 v2 = *(const float2*)(kfp + 2 * q);
            kfv[2 * q] = v2.x; kfv[2 * q + 1] = v2.y;
        }
        u64 kf2[8];
        #pragma unroll
        for (int fi = 0; fi < 8; fi++) kf2[fi] = frep2(kfv[fi]);
        const float* vmp = &s_vm[nn * 34 + dx * 8];
        u64 vm2[4];
        #pragma unroll
        for (int q = 0; q < 4; q++) vm2[q] = *(const u64*)(vmp + 2 * q);
        #pragma unroll
        for (int fi = 0; fi < 8; fi++)
            #pragma unroll
            for (int q = 0; q < 4; q++) ffma2(acc2[fi][q], kf2[fi], vm2[q]);
        if (dx == 0) {
            #pragma unroll
            for (int fi = 0; fi < 8; fi++) ks[fi] += kfv[fi];
        }
    }
    __syncthreads();   // everyone done READING s_kf/s_vm

    // ---- phase 2: spill partials into aliased regions + reload qf weights ----
    #pragma unroll
    for (int fi = 0; fi < 8; fi++) {
        float2 u0 = funpk(acc2[fi][0]), u1 = funpk(acc2[fi][1]);
        float2 u2 = funpk(acc2[fi][2]), u3 = funpk(acc2[fi][3]);
        float* dst = &s_kvp[w * 2048 + (fy * 8 + fi) * 32 + dx * 8];
        *(float4*)dst       = make_float4(u0.x, u0.y, u1.x, u1.y);
        *(float4*)(dst + 4) = make_float4(u2.x, u2.y, u3.x, u3.y);
    }
    if (dx == 0) {
        #pragma unroll
        for (int fi = 0; fi < 8; fi++) s_ksp[w * 64 + fy * 8 + fi] = ks[fi];
    }
    for (int i = tid; i < 1024; i += 256) s_w[i] = qfw[i];
    if (tid < 32) s_w[1024 + tid] = qfb[tid];
    __syncthreads();

    // ---- reduce partials -> s_kv, s_ks ----
    {
        int e = tid * 8;
        float4 r0 = make_float4(0, 0, 0, 0), r1 = make_float4(0, 0, 0, 0);
        #pragma unroll
        for (int w2 = 0; w2 < 8; w2++) {
            float4 p0 = *(const float4*)&s_kvp[w2 * 2048 + e];
            float4 p1 = *(const float4*)&s_kvp[w2 * 2048 + e + 4];
            r0.x += p0.x; r0.y += p0.y; r0.z += p0.z; r0.w += p0.w;
            r1.x += p1.x; r1.y += p1.y; r1.z += p1.z; r1.w += p1.w;
        }
        *(float4*)&s_kv[e]     = r0;
        *(float4*)&s_kv[e + 4] = r1;
        if (tid < 64) {
            float s = 0.0f;
            #pragma unroll
            for (int w2 = 0; w2 < 8; w2++) s += s_ksp[w2 * 64 + tid];
            s_ks[tid] = s;
        }
    }
    __syncthreads();

    // ---- step C: qf features streamed, num = qf @ kv (f32x2), denom, gate ----
    {
        float qvec[32];
        #pragma unroll
        for (int i = 0; i < 8; i++) {
            float4 v4 = *(const float4*)(Pt + 0 + i * 4);
            qvec[4 * i] = v4.x; qvec[4 * i + 1] = v4.y; qvec[4 * i + 2] = v4.z; qvec[4 * i + 3] = v4.w;
        }
        u64 num2[16];
        #pragma unroll
        for (int q = 0; q < 16; q++) num2[q] = 0ull;
        float den = 0.0f;
        #pragma unroll
        for (int jg = 0; jg < 4; jg++) {
            float a8[8];
            #pragma unroll
            for (int jj = 0; jj < 8; jj++) a8[jj] = s_w[1024 + jg * 8 + jj];
            #pragma unroll
            for (int d = 0; d < 32; d++) {
                float qd = qvec[d];
                #pragma unroll
                for (int jj = 0; jj < 8; jj++) a8[jj] += qd * s_w[(jg * 8 + jj) * 32 + d];
            }
            #pragma unroll
            for (int jj = 0; jj < 8; jj++) {
                float m = fminf(8.0f, fmaxf(-8.0f, a8[jj]));
                float e  = __expf(m);
                float ei = __expf(-m);
                int f1 = jg * 8 + jj, f2 = f1 + 32;
                den += e  * s_ks[f1];
                den += ei * s_ks[f2];
                u64 e2 = frep2(e), ei2 = frep2(ei);
                const ulonglong2* k1 = (const ulonglong2*)&s_kv[f1 * 32];
                const ulonglong2* k2 = (const ulonglong2*)&s_kv[f2 * 32];
                #pragma unroll
                for (int q = 0; q < 8; q++) {
                    ulonglong2 ka = k1[q];
                    ffma2(num2[2 * q],     e2, ka.x);
                    ffma2(num2[2 * q + 1], e2, ka.y);
                }
                #pragma unroll
                for (int q = 0; q < 8; q++) {
                    ulonglong2 kb = k2[q];
                    ffma2(num2[2 * q],     ei2, kb.x);
                    ffma2(num2[2 * q + 1], ei2, kb.y);
                }
            }
        }
        den = fmaxf(den, 1e-6f);
        float inv = 1.0f / den;
        float* GAt = g_GA + (size_t)t * 128 + h * 32;
        #pragma unroll
        for (int i = 0; i < 8; i++) {
            float4 g4 = *(const float4*)(Pt + 384 + i * 4);
            float2 ua = funpk(num2[2 * i]);
            float2 ub = funpk(num2[2 * i + 1]);
            float4 o4;
            o4.x = __fdividef(1.0f, 1.0f + __expf(-g4.x)) * ua.x * inv;
            o4.y = __fdividef(1.0f, 1.0f + __expf(-g4.y)) * ua.y * inv;
            o4.z = __fdividef(1.0f, 1.0f + __expf(-g4.z)) * ub.x * inv;
            o4.w = __fdividef(1.0f, 1.0f + __expf(-g4.w)) * ub.y * inv;
            *(float4*)(GAt + 4 * i) = o4;
        }
    }
}

// ---------------- launcher ----------------
extern "C" void kernel_launch(void* const* d_in, const int* in_sizes, int n_in,
                              void* d_out, int out_size) {
    const float* z    = (const float*)d_in[0];
    const int*   pm   = (const int*)  d_in[1];
    const float* lnw  = (const float*)d_in[2];
    const float* lnb  = (const float*)d_in[3];
    const float* qw   = (const float*)d_in[4];
    const float* qb   = (const float*)d_in[5];
    const float* kw   = (const float*)d_in[6];
    const float* kb   = (const float*)d_in[7];
    const float* vw   = (const float*)d_in[8];
    const float* vb   = (const float*)d_in[9];
    const float* qfw  = (const float*)d_in[10];
    const float* qfb  = (const float*)d_in[11];
    const float* kfw  = (const float*)d_in[12];
    const float* kfb  = (const float*)d_in[13];
    const float* gw   = (const float*)d_in[14];
    const float* gb   = (const float*)d_in[15];
    const float* ow   = (const float*)d_in[16];
    const float* ob   = (const float*)d_in[17];
    float* out = (float*)d_out;

    static int smem_set = 0;
    if (!smem_set) {
        cudaFuncSetAttribute(attn_kernel, cudaFuncAttributeMaxDynamicSharedMemorySize, 106624);
        smem_set = 1;
    }

    float* Wcat; cudaGetSymbolAddress((void**)&Wcat, g_Wcat);
    float* Bcat; cudaGetSymbolAddress((void**)&Bcat, g_Bcat);
    float* Zn;   cudaGetSymbolAddress((void**)&Zn,   g_zn);
    float* Pp;   cudaGetSymbolAddress((void**)&Pp,   g_P);
    float* GA;   cudaGetSymbolAddress((void**)&GA,   g_GA);

    pack_kernel<<<256, 256>>>(qw, kw, vw, gw, qb, kb, vb, gb);
    ln_kernel<<<8192, 256>>>(z, lnw, lnb);
    sgemm_k128<1><<<dim3(512, 4), 256>>>(Zn, Wcat, Bcat, nullptr, Pp, 512);
    attn_kernel<<<dim3(256, 4), 256, 106624>>>(pm, qfw, qfb, kfw, kfb);
    sgemm_k128<2><<<dim3(512, 1), 256>>>(GA, ow, ob, pm, out, 128);
}

// round 5
// speedup vs baseline: 1.7244x; 1.6198x over previous
#include <cuda_runtime.h>
#include <cuda_bf16.h>

// ---------------- scratch (static device memory; no allocation) ----------------
__device__ float         g_P [65536ull * 512];   // q|k|v|g projections (row-major)
__device__ float         g_GA[65536ull * 128];   // gate * attn_out (row-major)
__device__ __nv_bfloat16 g_znh[8388608];          // layernormed z hi [token][128]
__device__ __nv_bfloat16 g_znl[8388608];          // layernormed z lo
__device__ __nv_bfloat16 g_Wh[65536], g_Wl[65536];   // packed q|k|v|g weights [512][128]
__device__ __nv_bfloat16 g_Oh[16384], g_Ol[16384];   // o_w [128][128]
__device__ float         g_Bcat[512];                 // packed q|k|v|g biases

typedef unsigned long long u64;

// ---------------- f32x2 packed-FMA helpers ----------------
__device__ __forceinline__ u64 frep2(float x) {
    u64 r; asm("mov.b64 %0, {%1, %1};" : "=l"(r) : "f"(x)); return r;
}
__device__ __forceinline__ void ffma2(u64& d, u64 a, u64 b) {
    asm("fma.rn.f32x2 %0, %1, %2, %0;" : "+l"(d) : "l"(a), "l"(b));
}
__device__ __forceinline__ float2 funpk(u64 d) {
    float2 f; asm("mov.b64 {%0, %1}, %2;" : "=f"(f.x), "=f"(f.y) : "l"(d)); return f;
}

// ---------------- tensor-core helpers ----------------
__device__ __forceinline__ unsigned smem_u32p(const void* p) {
    return (unsigned)__cvta_generic_to_shared(p);
}
__device__ __forceinline__ void ldmx4(unsigned* r, unsigned addr) {
    asm volatile("ldmatrix.sync.aligned.m8n8.x4.shared.b16 {%0,%1,%2,%3}, [%4];"
        : "=r"(r[0]), "=r"(r[1]), "=r"(r[2]), "=r"(r[3]) : "r"(addr));
}
__device__ __forceinline__ void ldmx2(unsigned* r, unsigned addr) {
    asm volatile("ldmatrix.sync.aligned.m8n8.x2.shared.b16 {%0,%1}, [%2];"
        : "=r"(r[0]), "=r"(r[1]) : "r"(addr));
}
__device__ __forceinline__ void mma16816(float* c, const unsigned* a, const unsigned* b) {
    asm volatile("mma.sync.aligned.m16n8k16.row.col.f32.bf16.bf16.f32 "
        "{%0,%1,%2,%3}, {%4,%5,%6,%7}, {%8,%9}, {%0,%1,%2,%3};"
        : "+f"(c[0]), "+f"(c[1]), "+f"(c[2]), "+f"(c[3])
        : "r"(a[0]), "r"(a[1]), "r"(a[2]), "r"(a[3]), "r"(b[0]), "r"(b[1]));
}
__device__ __forceinline__ void bf16split(float x, __nv_bfloat16& h, __nv_bfloat16& l) {
    h = __float2bfloat16_rn(x);
    l = __float2bfloat16_rn(x - __bfloat162float(h));
}

// ---------------- K0: pack + split weights ----------------
__global__ void pack_kernel(const float* __restrict__ qw, const float* __restrict__ kw,
                            const float* __restrict__ vw, const float* __restrict__ gw,
                            const float* __restrict__ qb, const float* __restrict__ kb,
                            const float* __restrict__ vb, const float* __restrict__ gb,
                            const float* __restrict__ ow) {
    int idx = blockIdx.x * 256 + threadIdx.x;   // 0 .. 81919
    if (idx < 65536) {
        int row = idx >> 7, col = idx & 127;
        const float* w = (row < 128) ? qw : (row < 256) ? kw : (row < 384) ? vw : gw;
        float x = w[(row & 127) * 128 + col];
        __nv_bfloat16 h, l; bf16split(x, h, l);
        g_Wh[idx] = h; g_Wl[idx] = l;
        if (idx < 512) {
            const float* b = (idx < 128) ? qb : (idx < 256) ? kb : (idx < 384) ? vb : gb;
            g_Bcat[idx] = b[idx & 127];
        }
    } else if (idx < 81920) {
        int i = idx - 65536;
        __nv_bfloat16 h, l; bf16split(ow[i], h, l);
        g_Oh[i] = h; g_Ol[i] = l;
    }
}

// ---------------- K1: LayerNorm -> bf16 hi/lo ----------------
__global__ void ln_kernel(const float* __restrict__ z,
                          const float* __restrict__ lw,
                          const float* __restrict__ lb) {
    int warp = threadIdx.x >> 5, lane = threadIdx.x & 31;
    int t = blockIdx.x * 8 + warp;
    const float4* zp = (const float4*)(z + (size_t)t * 128);
    float4 v = zp[lane];
    float s = v.x + v.y + v.z + v.w;
    float q = v.x * v.x + v.y * v.y + v.z * v.z + v.w * v.w;
    #pragma unroll
    for (int o = 16; o; o >>= 1) {
        s += __shfl_xor_sync(0xFFFFFFFFu, s, o);
        q += __shfl_xor_sync(0xFFFFFFFFu, q, o);
    }
    float mu  = s * (1.0f / 128.0f);
    float var = q * (1.0f / 128.0f) - mu * mu;
    float rs  = rsqrtf(var + 1e-5f);
    float4 w4 = ((const float4*)lw)[lane];
    float4 b4 = ((const float4*)lb)[lane];
    float o4[4];
    o4[0] = (v.x - mu) * rs * w4.x + b4.x;
    o4[1] = (v.y - mu) * rs * w4.y + b4.y;
    o4[2] = (v.z - mu) * rs * w4.z + b4.z;
    o4[3] = (v.w - mu) * rs * w4.w + b4.w;
    __nv_bfloat16 h[4], l[4];
    #pragma unroll
    for (int i = 0; i < 4; i++) bf16split(o4[i], h[i], l[i]);
    size_t base = (size_t)t * 128 + lane * 4;
    *(__nv_bfloat162*)(g_znh + base)     = __nv_bfloat162(h[0], h[1]);
    *(__nv_bfloat162*)(g_znh + base + 2) = __nv_bfloat162(h[2], h[3]);
    *(__nv_bfloat162*)(g_znl + base)     = __nv_bfloat162(l[0], l[1]);
    *(__nv_bfloat162*)(g_znl + base + 2) = __nv_bfloat162(l[2], l[3]);
}

// ---------------- K2/K4: bf16-split tensor-core GEMM ----------------
// C[m][n] = sum_k A[m][k]*B[n][k] + bias[n], K=128, CTA tile 64x128, 8 warps 32x32.
// 3-term split: AhBh + AhBl + AlBh (fp32 accum).
// MODE 1 (proj): A = g_znh/g_znl, B = g_Wh/g_Wl, bias = g_Bcat, out -> g_P row-major.
// MODE 2 (out):  A = g_GA (fp32, converted on load), B = g_Oh/g_Ol, bias = ob,
//                out -> Cout row-major * mask[row].
template<int MODE>
__global__ void __launch_bounds__(256, 2) mma_gemm(const float* __restrict__ obias,
                                                   const int*   __restrict__ mask,
                                                   float* __restrict__ Cout) {
    extern __shared__ __nv_bfloat16 smem[];
    __nv_bfloat16* sAh = smem;             // 64*136
    __nv_bfloat16* sAl = smem + 8704;
    __nv_bfloat16* sBh = smem + 17408;     // 128*136
    __nv_bfloat16* sBl = smem + 34816;
    int tid = threadIdx.x;
    int bm0 = blockIdx.x * 64;
    int bn0 = (MODE == 1) ? blockIdx.y * 128 : 0;

    // --- load A tile (64 x 128) ---
    if (MODE == 1) {
        const uint4* srcH = (const uint4*)(g_znh + (size_t)bm0 * 128);
        const uint4* srcL = (const uint4*)(g_znl + (size_t)bm0 * 128);
        uint4* dAh = (uint4*)sAh; uint4* dAl = (uint4*)sAl;
        #pragma unroll
        for (int it = 0; it < 4; it++) {
            int idx = it * 256 + tid;          // 0..1023
            int row = idx >> 4, ch = idx & 15;
            dAh[row * 17 + ch] = srcH[idx];
            dAl[row * 17 + ch] = srcL[idx];
        }
    } else {
        const float4* srcA = (const float4*)(g_GA + (size_t)bm0 * 128);
        #pragma unroll
        for (int it = 0; it < 8; it++) {
            int idx = it * 256 + tid;          // 0..2047
            int row = idx >> 5, c4 = idx & 31;
            float4 v = srcA[idx];
            int col = c4 * 4;
            __nv_bfloat16 h, l;
            bf16split(v.x, h, l); sAh[row * 136 + col]     = h; sAl[row * 136 + col]     = l;
            bf16split(v.y, h, l); sAh[row * 136 + col + 1] = h; sAl[row * 136 + col + 1] = l;
            bf16split(v.z, h, l); sAh[row * 136 + col + 2] = h; sAl[row * 136 + col + 2] = l;
            bf16split(v.w, h, l); sAh[row * 136 + col + 3] = h; sAl[row * 136 + col + 3] = l;
        }
    }
    // --- load B tile (128 x 128) ---
    {
        const __nv_bfloat16* BH = (MODE == 1) ? g_Wh : g_Oh;
        const __nv_bfloat16* BL = (MODE == 1) ? g_Wl : g_Ol;
        const uint4* srcH = (const uint4*)(BH + (size_t)bn0 * 128);
        const uint4* srcL = (const uint4*)(BL + (size_t)bn0 * 128);
        uint4* dBh = (uint4*)sBh; uint4* dBl = (uint4*)sBl;
        #pragma unroll
        for (int it = 0; it < 8; it++) {
            int idx = it * 256 + tid;          // 0..2047
            int row = idx >> 4, ch = idx & 15;
            dBh[row * 17 + ch] = srcH[idx];
            dBl[row * 17 + ch] = srcL[idx];
        }
    }
    __syncthreads();

    int wid = tid >> 5, lane = tid & 31;
    int warp_m = (wid & 1) * 32, warp_n = (wid >> 1) * 32;
    unsigned baseAh = smem_u32p(sAh), baseAl = smem_u32p(sAl);
    unsigned baseBh = smem_u32p(sBh), baseBl = smem_u32p(sBl);
    int arow = warp_m + (lane & 15);
    int kofa = (lane >> 4) * 8;
    int brow = warp_n + (lane & 7);
    int kofb = ((lane >> 3) & 1) * 8;

    float acc[2][4][4];
    #pragma unroll
    for (int mi = 0; mi < 2; mi++)
        #pragma unroll
        for (int ni = 0; ni < 4; ni++)
            #pragma unroll
            for (int c = 0; c < 4; c++) acc[mi][ni][c] = 0.0f;

    #pragma unroll
    for (int ks = 0; ks < 8; ks++) {
        unsigned ah[2][4], al[2][4], bh[4][2], bl[4][2];
        #pragma unroll
        for (int mi = 0; mi < 2; mi++) {
            unsigned ao = (unsigned)((arow + mi * 16) * 272 + (ks * 16 + kofa) * 2);
            ldmx4(ah[mi], baseAh + ao);
            ldmx4(al[mi], baseAl + ao);
        }
        #pragma unroll
        for (int ni = 0; ni < 4; ni++) {
            unsigned bo = (unsigned)((brow + ni * 8) * 272 + (ks * 16 + kofb) * 2);
            ldmx2(bh[ni], baseBh + bo);
            ldmx2(bl[ni], baseBl + bo);
        }
        #pragma unroll
        for (int mi = 0; mi < 2; mi++)
            #pragma unroll
            for (int ni = 0; ni < 4; ni++) {
                mma16816(acc[mi][ni], ah[mi], bh[ni]);
                mma16816(acc[mi][ni], ah[mi], bl[ni]);
                mma16816(acc[mi][ni], al[mi], bh[ni]);
            }
    }

    // --- epilogue: direct row-major writes ---
    #pragma unroll
    for (int mi = 0; mi < 2; mi++)
        #pragma unroll
        for (int ni = 0; ni < 4; ni++) {
            int row = bm0 + warp_m + mi * 16 + (lane >> 2);
            int col = bn0 + warp_n + ni * 8 + (lane & 3) * 2;
            if (MODE == 1) {
                float b0 = g_Bcat[col], b1 = g_Bcat[col + 1];
                *(float2*)&g_P[(size_t)row * 512 + col] =
                    make_float2(acc[mi][ni][0] + b0, acc[mi][ni][1] + b1);
                *(float2*)&g_P[(size_t)(row + 8) * 512 + col] =
                    make_float2(acc[mi][ni][2] + b0, acc[mi][ni][3] + b1);
            } else {
                float b0 = obias[col], b1 = obias[col + 1];
                float m0 = (float)mask[row], m1 = (float)mask[row + 8];
                *(float2*)&Cout[(size_t)row * 128 + col] =
                    make_float2((acc[mi][ni][0] + b0) * m0, (acc[mi][ni][1] + b1) * m0);
                *(float2*)&Cout[(size_t)(row + 8) * 128 + col] =
                    make_float2((acc[mi][ni][2] + b0) * m1, (acc[mi][ni][3] + b1) * m1);
            }
        }
}

// ---------------- K3: per-(row, head) linear attention (round-3 verbatim) ----------------
// grid (256 rows, 4 heads), 256 threads, dynamic smem 106624 bytes -> 2 CTAs/SM.
__global__ void __launch_bounds__(256, 2) attn_kernel(const int*   __restrict__ pm,
                                                      const float* __restrict__ qfw,
                                                      const float* __restrict__ qfb,
                                                      const float* __restrict__ kfw,
                                                      const float* __restrict__ kfb) {
    extern __shared__ float sm[];
    float* s_kf  = sm;                  // [256][66]
    float* s_vm  = sm + 16896;          // [256][34]
    float* s_kvp = sm;                  // alias [8][2048]
    float* s_ksp = sm + 16896;          // alias [8][64]
    float* s_kv  = sm + 16896 + 512;    // [2048]
    float* s_ks  = sm + 16896 + 2560;   // [64]
    float* s_w   = sm + 25600;          // [1056]

    int tid = threadIdx.x;
    int r = blockIdx.x, h = blockIdx.y;

    for (int i = tid; i < 1024; i += 256) s_w[i] = kfw[i];
    if (tid < 32) s_w[1024 + tid] = kfb[tid];

    int n = tid;
    int t = r * 256 + n;
    float maskf = (float)pm[t];
    const float* Pt = g_P + (size_t)t * 512 + h * 32;

    __syncthreads();

    // ---- step A: kf = feature(k_h)*mask, vm = v_h*mask ----
    {
        float kvec[32];
        #pragma unroll
        for (int i = 0; i < 8; i++) {
            float4 v4 = *(const float4*)(Pt + 128 + i * 4);
            kvec[4 * i] = v4.x; kvec[4 * i + 1] = v4.y; kvec[4 * i + 2] = v4.z; kvec[4 * i + 3] = v4.w;
        }
        #pragma unroll
        for (int jg = 0; jg < 4; jg++) {
            float a8[8];
            #pragma unroll
            for (int jj = 0; jj < 8; jj++) a8[jj] = s_w[1024 + jg * 8 + jj];
            #pragma unroll
            for (int d = 0; d < 32; d++) {
                float kd = kvec[d];
                #pragma unroll
                for (int jj = 0; jj < 8; jj++) a8[jj] += kd * s_w[(jg * 8 + jj) * 32 + d];
            }
            #pragma unroll
            for (int jj = 0; jj < 8; jj++) {
                float m = fminf(8.0f, fmaxf(-8.0f, a8[jj]));
                s_kf[n * 66 + jg * 8 + jj]      = __expf(m)  * maskf;
                s_kf[n * 66 + 32 + jg * 8 + jj] = __expf(-m) * maskf;
            }
        }
        #pragma unroll
        for (int i = 0; i < 8; i++) {
            float4 v4 = *(const float4*)(Pt + 256 + i * 4);
            *(float2*)&s_vm[n * 34 + 4 * i]     = make_float2(v4.x * maskf, v4.y * maskf);
            *(float2*)&s_vm[n * 34 + 4 * i + 2] = make_float2(v4.z * maskf, v4.w * maskf);
        }
    }
    __syncthreads();

    // ---- step B: per-warp partial kv[64][32] (f32x2) + ksum, in registers ----
    int lane = tid & 31, w = tid >> 5;
    int fy = lane >> 2, dx = lane & 3;          // f base = fy*8, d base = dx*8
    u64 acc2[8][4];
    float ks[8];
    #pragma unroll
    for (int fi = 0; fi < 8; fi++) {
        ks[fi] = 0.0f;
        #pragma unroll
        for (int q = 0; q < 4; q++) acc2[fi][q] = 0ull;
    }
    #pragma unroll 2
    for (int i = 0; i < 32; i++) {
        int nn = w * 32 + i;
        const float* kfp = &s_kf[nn * 66 + fy * 8];
        float kfv[8];
        #pragma unroll
        for (int q = 0; q < 4; q++) {
            float2 v2 = *(const float2*)(kfp + 2 * q);
            kfv[2 * q] = v2.x; kfv[2 * q + 1] = v2.y;
        }
        u64 kf2[8];
        #pragma unroll
        for (int fi = 0; fi < 8; fi++) kf2[fi] = frep2(kfv[fi]);
        const float* vmp = &s_vm[nn * 34 + dx * 8];
        u64 vm2[4];
        #pragma unroll
        for (int q = 0; q < 4; q++) vm2[q] = *(const u64*)(vmp + 2 * q);
        #pragma unroll
        for (int fi = 0; fi < 8; fi++)
            #pragma unroll
            for (int q = 0; q < 4; q++) ffma2(acc2[fi][q], kf2[fi], vm2[q]);
        if (dx == 0) {
            #pragma unroll
            for (int fi = 0; fi < 8; fi++) ks[fi] += kfv[fi];
        }
    }
    __syncthreads();   // everyone done READING s_kf/s_vm

    // ---- phase 2: spill partials into aliased regions + reload qf weights ----
    #pragma unroll
    for (int fi = 0; fi < 8; fi++) {
        float2 u0 = funpk(acc2[fi][0]), u1 = funpk(acc2[fi][1]);
        float2 u2 = funpk(acc2[fi][2]), u3 = funpk(acc2[fi][3]);
        float* dst = &s_kvp[w * 2048 + (fy * 8 + fi) * 32 + dx * 8];
        *(float4*)dst       = make_float4(u0.x, u0.y, u1.x, u1.y);
        *(float4*)(dst + 4) = make_float4(u2.x, u2.y, u3.x, u3.y);
    }
    if (dx == 0) {
        #pragma unroll
        for (int fi = 0; fi < 8; fi++) s_ksp[w * 64 + fy * 8 + fi] = ks[fi];
    }
    for (int i = tid; i < 1024; i += 256) s_w[i] = qfw[i];
    if (tid < 32) s_w[1024 + tid] = qfb[tid];
    __syncthreads();

    // ---- reduce partials -> s_kv, s_ks ----
    {
        int e = tid * 8;
        float4 r0 = make_float4(0, 0, 0, 0), r1 = make_float4(0, 0, 0, 0);
        #pragma unroll
        for (int w2 = 0; w2 < 8; w2++) {
            float4 p0 = *(const float4*)&s_kvp[w2 * 2048 + e];
            float4 p1 = *(const float4*)&s_kvp[w2 * 2048 + e + 4];
            r0.x += p0.x; r0.y += p0.y; r0.z += p0.z; r0.w += p0.w;
            r1.x += p1.x; r1.y += p1.y; r1.z += p1.z; r1.w += p1.w;
        }
        *(float4*)&s_kv[e]     = r0;
        *(float4*)&s_kv[e + 4] = r1;
        if (tid < 64) {
            float s = 0.0f;
            #pragma unroll
            for (int w2 = 0; w2 < 8; w2++) s += s_ksp[w2 * 64 + tid];
            s_ks[tid] = s;
        }
    }
    __syncthreads();

    // ---- step C: qf features streamed, num = qf @ kv (f32x2), denom, gate ----
    {
        float qvec[32];
        #pragma unroll
        for (int i = 0; i < 8; i++) {
            float4 v4 = *(const float4*)(Pt + 0 + i * 4);
            qvec[4 * i] = v4.x; qvec[4 * i + 1] = v4.y; qvec[4 * i + 2] = v4.z; qvec[4 * i + 3] = v4.w;
        }
        u64 num2[16];
        #pragma unroll
        for (int q = 0; q < 16; q++) num2[q] = 0ull;
        float den = 0.0f;
        #pragma unroll
        for (int jg = 0; jg < 4; jg++) {
            float a8[8];
            #pragma unroll
            for (int jj = 0; jj < 8; jj++) a8[jj] = s_w[1024 + jg * 8 + jj];
            #pragma unroll
            for (int d = 0; d < 32; d++) {
                float qd = qvec[d];
                #pragma unroll
                for (int jj = 0; jj < 8; jj++) a8[jj] += qd * s_w[(jg * 8 + jj) * 32 + d];
            }
            #pragma unroll
            for (int jj = 0; jj < 8; jj++) {
                float m = fminf(8.0f, fmaxf(-8.0f, a8[jj]));
                float e  = __expf(m);
                float ei = __expf(-m);
                int f1 = jg * 8 + jj, f2 = f1 + 32;
                den += e  * s_ks[f1];
                den += ei * s_ks[f2];
                u64 e2 = frep2(e), ei2 = frep2(ei);
                const ulonglong2* k1 = (const ulonglong2*)&s_kv[f1 * 32];
                const ulonglong2* k2 = (const ulonglong2*)&s_kv[f2 * 32];
                #pragma unroll
                for (int q = 0; q < 8; q++) {
                    ulonglong2 ka = k1[q];
                    ffma2(num2[2 * q],     e2, ka.x);
                    ffma2(num2[2 * q + 1], e2, ka.y);
                }
                #pragma unroll
                for (int q = 0; q < 8; q++) {
                    ulonglong2 kb = k2[q];
                    ffma2(num2[2 * q],     ei2, kb.x);
                    ffma2(num2[2 * q + 1], ei2, kb.y);
                }
            }
        }
        den = fmaxf(den, 1e-6f);
        float inv = 1.0f / den;
        float* GAt = g_GA + (size_t)t * 128 + h * 32;
        #pragma unroll
        for (int i = 0; i < 8; i++) {
            float4 g4 = *(const float4*)(Pt + 384 + i * 4);
            float2 ua = funpk(num2[2 * i]);
            float2 ub = funpk(num2[2 * i + 1]);
            float4 o4;
            o4.x = __fdividef(1.0f, 1.0f + __expf(-g4.x)) * ua.x * inv;
            o4.y = __fdividef(1.0f, 1.0f + __expf(-g4.y)) * ua.y * inv;
            o4.z = __fdividef(1.0f, 1.0f + __expf(-g4.z)) * ub.x * inv;
            o4.w = __fdividef(1.0f, 1.0f + __expf(-g4.w)) * ub.y * inv;
            *(float4*)(GAt + 4 * i) = o4;
        }
    }
}

// ---------------- launcher ----------------
extern "C" void kernel_launch(void* const* d_in, const int* in_sizes, int n_in,
                              void* d_out, int out_size) {
    const float* z    = (const float*)d_in[0];
    const int*   pm   = (const int*)  d_in[1];
    const float* lnw  = (const float*)d_in[2];
    const float* lnb  = (const float*)d_in[3];
    const float* qw   = (const float*)d_in[4];
    const float* qb   = (const float*)d_in[5];
    const float* kw   = (const float*)d_in[6];
    const float* kb   = (const float*)d_in[7];
    const float* vw   = (const float*)d_in[8];
    const float* vb   = (const float*)d_in[9];
    const float* qfw  = (const float*)d_in[10];
    const float* qfb  = (const float*)d_in[11];
    const float* kfw  = (const float*)d_in[12];
    const float* kfb  = (const float*)d_in[13];
    const float* gw   = (const float*)d_in[14];
    const float* gb   = (const float*)d_in[15];
    const float* ow   = (const float*)d_in[16];
    const float* ob   = (const float*)d_in[17];
    float* out = (float*)d_out;

    static int attr_set = 0;
    if (!attr_set) {
        cudaFuncSetAttribute(attn_kernel, cudaFuncAttributeMaxDynamicSharedMemorySize, 106624);
        cudaFuncSetAttribute(mma_gemm<1>, cudaFuncAttributeMaxDynamicSharedMemorySize, 104448);
        cudaFuncSetAttribute(mma_gemm<2>, cudaFuncAttributeMaxDynamicSharedMemorySize, 104448);
        attr_set = 1;
    }

    pack_kernel<<<320, 256>>>(qw, kw, vw, gw, qb, kb, vb, gb, ow);
    ln_kernel<<<8192, 256>>>(z, lnw, lnb);
    mma_gemm<1><<<dim3(1024, 4), 256, 104448>>>(nullptr, nullptr, nullptr);
    attn_kernel<<<dim3(256, 4), 256, 106624>>>(pm, qfw, qfb, kfw, kfb);
    mma_gemm<2><<<dim3(1024, 1), 256, 104448>>>(ob, pm, out);
}

// round 6
// speedup vs baseline: 1.8951x; 1.0990x over previous
#include <cuda_runtime.h>
#include <cuda_bf16.h>

// ---------------- scratch (static device memory; no allocation) ----------------
__device__ float         g_P [65536ull * 512];   // q|k|v|g projections (row-major)
__device__ float         g_GA[65536ull * 128];   // gate * attn_out (row-major)
__device__ __nv_bfloat16 g_znh[8388608];          // layernormed z hi [token][128]
__device__ __nv_bfloat16 g_znl[8388608];          // layernormed z lo
__device__ __nv_bfloat16 g_Wh[65536], g_Wl[65536];   // packed q|k|v|g weights [512][128]
__device__ __nv_bfloat16 g_Oh[16384], g_Ol[16384];   // o_w [128][128]
__device__ float         g_Bcat[512];                 // packed q|k|v|g biases

typedef unsigned long long u64;

// ---------------- f32x2 packed-FMA helpers ----------------
__device__ __forceinline__ u64 frep2(float x) {
    u64 r; asm("mov.b64 %0, {%1, %1};" : "=l"(r) : "f"(x)); return r;
}
__device__ __forceinline__ void ffma2(u64& d, u64 a, u64 b) {
    asm("fma.rn.f32x2 %0, %1, %2, %0;" : "+l"(d) : "l"(a), "l"(b));
}
__device__ __forceinline__ float2 funpk(u64 d) {
    float2 f; asm("mov.b64 {%0, %1}, %2;" : "=f"(f.x), "=f"(f.y) : "l"(d)); return f;
}

// ---------------- tensor-core helpers ----------------
__device__ __forceinline__ unsigned smem_u32p(const void* p) {
    return (unsigned)__cvta_generic_to_shared(p);
}
__device__ __forceinline__ void ldmx4(unsigned* r, unsigned addr) {
    asm volatile("ldmatrix.sync.aligned.m8n8.x4.shared.b16 {%0,%1,%2,%3}, [%4];"
        : "=r"(r[0]), "=r"(r[1]), "=r"(r[2]), "=r"(r[3]) : "r"(addr));
}
__device__ __forceinline__ void ldmx2(unsigned* r, unsigned addr) {
    asm volatile("ldmatrix.sync.aligned.m8n8.x2.shared.b16 {%0,%1}, [%2];"
        : "=r"(r[0]), "=r"(r[1]) : "r"(addr));
}
__device__ __forceinline__ void mma16816(float* c, const unsigned* a, const unsigned* b) {
    asm volatile("mma.sync.aligned.m16n8k16.row.col.f32.bf16.bf16.f32 "
        "{%0,%1,%2,%3}, {%4,%5,%6,%7}, {%8,%9}, {%0,%1,%2,%3};"
        : "+f"(c[0]), "+f"(c[1]), "+f"(c[2]), "+f"(c[3])
        : "r"(a[0]), "r"(a[1]), "r"(a[2]), "r"(a[3]), "r"(b[0]), "r"(b[1]));
}
__device__ __forceinline__ void bf16split(float x, __nv_bfloat16& h, __nv_bfloat16& l) {
    h = __float2bfloat16_rn(x);
    l = __float2bfloat16_rn(x - __bfloat162float(h));
}

// ---------------- K0: pack + split weights ----------------
__global__ void pack_kernel(const float* __restrict__ qw, const float* __restrict__ kw,
                            const float* __restrict__ vw, const float* __restrict__ gw,
                            const float* __restrict__ qb, const float* __restrict__ kb,
                            const float* __restrict__ vb, const float* __restrict__ gb,
                            const float* __restrict__ ow) {
    int idx = blockIdx.x * 256 + threadIdx.x;   // 0 .. 81919
    if (idx < 65536) {
        int row = idx >> 7, col = idx & 127;
        const float* w = (row < 128) ? qw : (row < 256) ? kw : (row < 384) ? vw : gw;
        float x = w[(row & 127) * 128 + col];
        __nv_bfloat16 h, l; bf16split(x, h, l);
        g_Wh[idx] = h; g_Wl[idx] = l;
        if (idx < 512) {
            const float* b = (idx < 128) ? qb : (idx < 256) ? kb : (idx < 384) ? vb : gb;
            g_Bcat[idx] = b[idx & 127];
        }
    } else if (idx < 81920) {
        int i = idx - 65536;
        __nv_bfloat16 h, l; bf16split(ow[i], h, l);
        g_Oh[i] = h; g_Ol[i] = l;
    }
}

// ---------------- K1: LayerNorm -> bf16 hi/lo ----------------
__global__ void ln_kernel(const float* __restrict__ z,
                          const float* __restrict__ lw,
                          const float* __restrict__ lb) {
    int warp = threadIdx.x >> 5, lane = threadIdx.x & 31;
    int t = blockIdx.x * 8 + warp;
    const float4* zp = (const float4*)(z + (size_t)t * 128);
    float4 v = zp[lane];
    float s = v.x + v.y + v.z + v.w;
    float q = v.x * v.x + v.y * v.y + v.z * v.z + v.w * v.w;
    #pragma unroll
    for (int o = 16; o; o >>= 1) {
        s += __shfl_xor_sync(0xFFFFFFFFu, s, o);
        q += __shfl_xor_sync(0xFFFFFFFFu, q, o);
    }
    float mu  = s * (1.0f / 128.0f);
    float var = q * (1.0f / 128.0f) - mu * mu;
    float rs  = rsqrtf(var + 1e-5f);
    float4 w4 = ((const float4*)lw)[lane];
    float4 b4 = ((const float4*)lb)[lane];
    float o4[4];
    o4[0] = (v.x - mu) * rs * w4.x + b4.x;
    o4[1] = (v.y - mu) * rs * w4.y + b4.y;
    o4[2] = (v.z - mu) * rs * w4.z + b4.z;
    o4[3] = (v.w - mu) * rs * w4.w + b4.w;
    __nv_bfloat16 h[4], l[4];
    #pragma unroll
    for (int i = 0; i < 4; i++) bf16split(o4[i], h[i], l[i]);
    size_t base = (size_t)t * 128 + lane * 4;
    *(__nv_bfloat162*)(g_znh + base)     = __nv_bfloat162(h[0], h[1]);
    *(__nv_bfloat162*)(g_znh + base + 2) = __nv_bfloat162(h[2], h[3]);
    *(__nv_bfloat162*)(g_znl + base)     = __nv_bfloat162(l[0], l[1]);
    *(__nv_bfloat162*)(g_znl + base + 2) = __nv_bfloat162(l[2], l[3]);
}

// ---------------- K2/K4: bf16-split tensor-core GEMM (round-5 verbatim) ----------------
template<int MODE>
__global__ void __launch_bounds__(256, 2) mma_gemm(const float* __restrict__ obias,
                                                   const int*   __restrict__ mask,
                                                   float* __restrict__ Cout) {
    extern __shared__ __nv_bfloat16 smem[];
    __nv_bfloat16* sAh = smem;             // 64*136
    __nv_bfloat16* sAl = smem + 8704;
    __nv_bfloat16* sBh = smem + 17408;     // 128*136
    __nv_bfloat16* sBl = smem + 34816;
    int tid = threadIdx.x;
    int bm0 = blockIdx.x * 64;
    int bn0 = (MODE == 1) ? blockIdx.y * 128 : 0;

    if (MODE == 1) {
        const uint4* srcH = (const uint4*)(g_znh + (size_t)bm0 * 128);
        const uint4* srcL = (const uint4*)(g_znl + (size_t)bm0 * 128);
        uint4* dAh = (uint4*)sAh; uint4* dAl = (uint4*)sAl;
        #pragma unroll
        for (int it = 0; it < 4; it++) {
            int idx = it * 256 + tid;
            int row = idx >> 4, ch = idx & 15;
            dAh[row * 17 + ch] = srcH[idx];
            dAl[row * 17 + ch] = srcL[idx];
        }
    } else {
        const float4* srcA = (const float4*)(g_GA + (size_t)bm0 * 128);
        #pragma unroll
        for (int it = 0; it < 8; it++) {
            int idx = it * 256 + tid;
            int row = idx >> 5, c4 = idx & 31;
            float4 v = srcA[idx];
            int col = c4 * 4;
            __nv_bfloat16 h, l;
            bf16split(v.x, h, l); sAh[row * 136 + col]     = h; sAl[row * 136 + col]     = l;
            bf16split(v.y, h, l); sAh[row * 136 + col + 1] = h; sAl[row * 136 + col + 1] = l;
            bf16split(v.z, h, l); sAh[row * 136 + col + 2] = h; sAl[row * 136 + col + 2] = l;
            bf16split(v.w, h, l); sAh[row * 136 + col + 3] = h; sAl[row * 136 + col + 3] = l;
        }
    }
    {
        const __nv_bfloat16* BH = (MODE == 1) ? g_Wh : g_Oh;
        const __nv_bfloat16* BL = (MODE == 1) ? g_Wl : g_Ol;
        const uint4* srcH = (const uint4*)(BH + (size_t)bn0 * 128);
        const uint4* srcL = (const uint4*)(BL + (size_t)bn0 * 128);
        uint4* dBh = (uint4*)sBh; uint4* dBl = (uint4*)sBl;
        #pragma unroll
        for (int it = 0; it < 8; it++) {
            int idx = it * 256 + tid;
            int row = idx >> 4, ch = idx & 15;
            dBh[row * 17 + ch] = srcH[idx];
            dBl[row * 17 + ch] = srcL[idx];
        }
    }
    __syncthreads();

    int wid = tid >> 5, lane = tid & 31;
    int warp_m = (wid & 1) * 32, warp_n = (wid >> 1) * 32;
    unsigned baseAh = smem_u32p(sAh), baseAl = smem_u32p(sAl);
    unsigned baseBh = smem_u32p(sBh), baseBl = smem_u32p(sBl);
    int arow = warp_m + (lane & 15);
    int kofa = (lane >> 4) * 8;
    int brow = warp_n + (lane & 7);
    int kofb = ((lane >> 3) & 1) * 8;

    float acc[2][4][4];
    #pragma unroll
    for (int mi = 0; mi < 2; mi++)
        #pragma unroll
        for (int ni = 0; ni < 4; ni++)
            #pragma unroll
            for (int c = 0; c < 4; c++) acc[mi][ni][c] = 0.0f;

    #pragma unroll
    for (int ks = 0; ks < 8; ks++) {
        unsigned ah[2][4], al[2][4], bh[4][2], bl[4][2];
        #pragma unroll
        for (int mi = 0; mi < 2; mi++) {
            unsigned ao = (unsigned)((arow + mi * 16) * 272 + (ks * 16 + kofa) * 2);
            ldmx4(ah[mi], baseAh + ao);
            ldmx4(al[mi], baseAl + ao);
        }
        #pragma unroll
        for (int ni = 0; ni < 4; ni++) {
            unsigned bo = (unsigned)((brow + ni * 8) * 272 + (ks * 16 + kofb) * 2);
            ldmx2(bh[ni], baseBh + bo);
            ldmx2(bl[ni], baseBl + bo);
        }
        #pragma unroll
        for (int mi = 0; mi < 2; mi++)
            #pragma unroll
            for (int ni = 0; ni < 4; ni++) {
                mma16816(acc[mi][ni], ah[mi], bh[ni]);
                mma16816(acc[mi][ni], ah[mi], bl[ni]);
                mma16816(acc[mi][ni], al[mi], bh[ni]);
            }
    }

    #pragma unroll
    for (int mi = 0; mi < 2; mi++)
        #pragma unroll
        for (int ni = 0; ni < 4; ni++) {
            int row = bm0 + warp_m + mi * 16 + (lane >> 2);
            int col = bn0 + warp_n + ni * 8 + (lane & 3) * 2;
            if (MODE == 1) {
                float b0 = g_Bcat[col], b1 = g_Bcat[col + 1];
                *(float2*)&g_P[(size_t)row * 512 + col] =
                    make_float2(acc[mi][ni][0] + b0, acc[mi][ni][1] + b1);
                *(float2*)&g_P[(size_t)(row + 8) * 512 + col] =
                    make_float2(acc[mi][ni][2] + b0, acc[mi][ni][3] + b1);
            } else {
                float b0 = obias[col], b1 = obias[col + 1];
                float m0 = (float)mask[row], m1 = (float)mask[row + 8];
                *(float2*)&Cout[(size_t)row * 128 + col] =
                    make_float2((acc[mi][ni][0] + b0) * m0, (acc[mi][ni][1] + b1) * m0);
                *(float2*)&Cout[(size_t)(row + 8) * 128 + col] =
                    make_float2((acc[mi][ni][2] + b0) * m1, (acc[mi][ni][3] + b1) * m1);
            }
        }
}

// ---------------- K3: per-(row, head) linear attention — coalesced staging ----------------
// grid (256 rows, 4 heads), 256 threads, dynamic smem 107648 B -> 2 CTAs/SM.
// regions (floats):
//   A: sm[0..16896)    s_kf[256][66]; later s_kvp[8][2048]; later s_q[256][33]+s_g[256][33]; later s_out
//   B: sm[16896..25600) k-stage[256][33] -> s_vm[256][34]; later s_ksp[512]+s_kv[2048]+s_ks[64]
//   C: sm[25600..26656) s_w[1056];  sm[26656..26912) s_mask[256]
__global__ void __launch_bounds__(256, 2) attn_kernel(const int*   __restrict__ pm,
                                                      const float* __restrict__ qfw,
                                                      const float* __restrict__ qfb,
                                                      const float* __restrict__ kfw,
                                                      const float* __restrict__ kfb) {
    extern __shared__ float sm[];
    float* s_kf    = sm;              // [256][66]
    float* s_stage = sm + 16896;      // k-stage [256][33]
    float* s_vm    = sm + 16896;      // v [256][34]
    float* s_kvp   = sm;              // alias [8][2048]
    float* s_ksp   = sm + 16896;      // [8][64]
    float* s_kv    = sm + 17408;      // [2048]
    float* s_ks    = sm + 19456;      // [64]
    float* s_w     = sm + 25600;      // [1056]
    float* s_mask  = sm + 26656;      // [256]
    float* s_q     = sm;              // [256][33] (after reduce)
    float* s_g     = sm + 8448;       // [256][33]
    float* s_out   = sm;              // [256][33] (after q consumed)

    int tid = threadIdx.x;
    int r = blockIdx.x, h = blockIdx.y;
    int t0 = r * 256;
    int t  = t0 + tid;

    for (int i = tid; i < 1024; i += 256) s_w[i] = kfw[i];
    if (tid < 32) s_w[1024 + tid] = kfb[tid];
    float maskf = (float)pm[t];
    s_mask[tid] = maskf;

    // ---- coop load k-slice (coalesced) -> s_stage stride 33 ----
    {
        const float* Pk0 = g_P + (size_t)t0 * 512 + 128 + h * 32;
        #pragma unroll
        for (int it = 0; it < 8; it++) {
            int idx = it * 256 + tid;
            int token = idx >> 3, c4 = idx & 7;
            float4 v = *(const float4*)(Pk0 + (size_t)token * 512 + c4 * 4);
            float* d = s_stage + token * 33 + c4 * 4;
            d[0] = v.x; d[1] = v.y; d[2] = v.z; d[3] = v.w;
        }
    }
    __syncthreads();

    // ---- step A: kf = feature(k)*mask ----
    {
        float kvec[32];
        #pragma unroll
        for (int d = 0; d < 32; d++) kvec[d] = s_stage[tid * 33 + d];
        #pragma unroll
        for (int jg = 0; jg < 4; jg++) {
            float a8[8];
            #pragma unroll
            for (int jj = 0; jj < 8; jj++) a8[jj] = s_w[1024 + jg * 8 + jj];
            #pragma unroll
            for (int d = 0; d < 32; d++) {
                float kd = kvec[d];
                #pragma unroll
                for (int jj = 0; jj < 8; jj++) a8[jj] += kd * s_w[(jg * 8 + jj) * 32 + d];
            }
            #pragma unroll
            for (int jj = 0; jj < 8; jj++) {
                float m = fminf(8.0f, fmaxf(-8.0f, a8[jj]));
                s_kf[tid * 66 + jg * 8 + jj]      = __expf(m)  * maskf;
                s_kf[tid * 66 + 32 + jg * 8 + jj] = __expf(-m) * maskf;
            }
        }
    }
    __syncthreads();   // all threads done reading k-stage

    // ---- coop load v-slice * mask (coalesced) -> s_vm stride 34 ----
    {
        const float* Pv0 = g_P + (size_t)t0 * 512 + 256 + h * 32;
        #pragma unroll
        for (int it = 0; it < 8; it++) {
            int idx = it * 256 + tid;
            int token = idx >> 3, c4 = idx & 7;
            float4 v = *(const float4*)(Pv0 + (size_t)token * 512 + c4 * 4);
            float m = s_mask[token];
            float* d = s_vm + token * 34 + c4 * 4;
            d[0] = v.x * m; d[1] = v.y * m; d[2] = v.z * m; d[3] = v.w * m;
        }
    }
    __syncthreads();

    // ---- step B: per-warp partial kv[64][32] (f32x2) + ksum, in registers ----
    int lane = tid & 31, w = tid >> 5;
    int fy = lane >> 2, dx = lane & 3;
    u64 acc2[8][4];
    float ks[8];
    #pragma unroll
    for (int fi = 0; fi < 8; fi++) {
        ks[fi] = 0.0f;
        #pragma unroll
        for (int q = 0; q < 4; q++) acc2[fi][q] = 0ull;
    }
    #pragma unroll 2
    for (int i = 0; i < 32; i++) {
        int nn = w * 32 + i;
        const float* kfp = &s_kf[nn * 66 + fy * 8];
        float kfv[8];
        #pragma unroll
        for (int q = 0; q < 4; q++) {
            float2 v2 = *(const float2*)(kfp + 2 * q);
            kfv[2 * q] = v2.x; kfv[2 * q + 1] = v2.y;
        }
        u64 kf2[8];
        #pragma unroll
        for (int fi = 0; fi < 8; fi++) kf2[fi] = frep2(kfv[fi]);
        const float* vmp = &s_vm[nn * 34 + dx * 8];
        u64 vm2[4];
        #pragma unroll
        for (int q = 0; q < 4; q++) vm2[q] = *(const u64*)(vmp + 2 * q);
        #pragma unroll
        for (int fi = 0; fi < 8; fi++)
            #pragma unroll
            for (int q = 0; q < 4; q++) ffma2(acc2[fi][q], kf2[fi], vm2[q]);
        if (dx == 0) {
            #pragma unroll
            for (int fi = 0; fi < 8; fi++) ks[fi] += kfv[fi];
        }
    }
    __syncthreads();   // done reading s_kf / s_vm

    // ---- spill partials + reload qf weights ----
    #pragma unroll
    for (int fi = 0; fi < 8; fi++) {
        float2 u0 = funpk(acc2[fi][0]), u1 = funpk(acc2[fi][1]);
        float2 u2 = funpk(acc2[fi][2]), u3 = funpk(acc2[fi][3]);
        float* dst = &s_kvp[w * 2048 + (fy * 8 + fi) * 32 + dx * 8];
        *(float4*)dst       = make_float4(u0.x, u0.y, u1.x, u1.y);
        *(float4*)(dst + 4) = make_float4(u2.x, u2.y, u3.x, u3.y);
    }
    if (dx == 0) {
        #pragma unroll
        for (int fi = 0; fi < 8; fi++) s_ksp[w * 64 + fy * 8 + fi] = ks[fi];
    }
    for (int i = tid; i < 1024; i += 256) s_w[i] = qfw[i];
    if (tid < 32) s_w[1024 + tid] = qfb[tid];
    __syncthreads();

    // ---- reduce partials -> s_kv, s_ks ----
    {
        int e = tid * 8;
        float4 r0 = make_float4(0, 0, 0, 0), r1 = make_float4(0, 0, 0, 0);
        #pragma unroll
        for (int w2 = 0; w2 < 8; w2++) {
            float4 p0 = *(const float4*)&s_kvp[w2 * 2048 + e];
            float4 p1 = *(const float4*)&s_kvp[w2 * 2048 + e + 4];
            r0.x += p0.x; r0.y += p0.y; r0.z += p0.z; r0.w += p0.w;
            r1.x += p1.x; r1.y += p1.y; r1.z += p1.z; r1.w += p1.w;
        }
        *(float4*)&s_kv[e]     = r0;
        *(float4*)&s_kv[e + 4] = r1;
        if (tid < 64) {
            float s = 0.0f;
            #pragma unroll
            for (int w2 = 0; w2 < 8; w2++) s += s_ksp[w2 * 64 + tid];
            s_ks[tid] = s;
        }
    }
    __syncthreads();

    // ---- coop load q-slice and g-slice (coalesced) -> s_q, s_g stride 33 ----
    {
        const float* Pq0 = g_P + (size_t)t0 * 512 + h * 32;
        const float* Pg0 = g_P + (size_t)t0 * 512 + 384 + h * 32;
        #pragma unroll
        for (int it = 0; it < 8; it++) {
            int idx = it * 256 + tid;
            int token = idx >> 3, c4 = idx & 7;
            float4 a = *(const float4*)(Pq0 + (size_t)token * 512 + c4 * 4);
            float4 b = *(const float4*)(Pg0 + (size_t)token * 512 + c4 * 4);
            float* dq = s_q + token * 33 + c4 * 4;
            dq[0] = a.x; dq[1] = a.y; dq[2] = a.z; dq[3] = a.w;
            float* dg = s_g + token * 33 + c4 * 4;
            dg[0] = b.x; dg[1] = b.y; dg[2] = b.z; dg[3] = b.w;
        }
    }
    __syncthreads();

    // ---- step C: qf features, num = qf @ kv (f32x2), denom, gate -> vals ----
    float vals[32];
    {
        float qvec[32];
        #pragma unroll
        for (int d = 0; d < 32; d++) qvec[d] = s_q[tid * 33 + d];
        u64 num2[16];
        #pragma unroll
        for (int q = 0; q < 16; q++) num2[q] = 0ull;
        float den = 0.0f;
        #pragma unroll
        for (int jg = 0; jg < 4; jg++) {
            float a8[8];
            #pragma unroll
            for (int jj = 0; jj < 8; jj++) a8[jj] = s_w[1024 + jg * 8 + jj];
            #pragma unroll
            for (int d = 0; d < 32; d++) {
                float qd = qvec[d];
                #pragma unroll
                for (int jj = 0; jj < 8; jj++) a8[jj] += qd * s_w[(jg * 8 + jj) * 32 + d];
            }
            #pragma unroll
            for (int jj = 0; jj < 8; jj++) {
                float m = fminf(8.0f, fmaxf(-8.0f, a8[jj]));
                float e  = __expf(m);
                float ei = __expf(-m);
                int f1 = jg * 8 + jj, f2 = f1 + 32;
                den += e  * s_ks[f1];
                den += ei * s_ks[f2];
                u64 e2 = frep2(e), ei2 = frep2(ei);
                const ulonglong2* k1 = (const ulonglong2*)&s_kv[f1 * 32];
                const ulonglong2* k2 = (const ulonglong2*)&s_kv[f2 * 32];
                #pragma unroll
                for (int q = 0; q < 8; q++) {
                    ulonglong2 ka = k1[q];
                    ffma2(num2[2 * q],     e2, ka.x);
                    ffma2(num2[2 * q + 1], e2, ka.y);
                }
                #pragma unroll
                for (int q = 0; q < 8; q++) {
                    ulonglong2 kb = k2[q];
                    ffma2(num2[2 * q],     ei2, kb.x);
                    ffma2(num2[2 * q + 1], ei2, kb.y);
                }
            }
        }
        den = fmaxf(den, 1e-6f);
        float inv = 1.0f / den;
        #pragma unroll
        for (int i = 0; i < 8; i++) {
            float2 ua = funpk(num2[2 * i]);
            float2 ub = funpk(num2[2 * i + 1]);
            float g0 = s_g[tid * 33 + 4 * i + 0];
            float g1 = s_g[tid * 33 + 4 * i + 1];
            float g2 = s_g[tid * 33 + 4 * i + 2];
            float g3 = s_g[tid * 33 + 4 * i + 3];
            vals[4 * i + 0] = __fdividef(1.0f, 1.0f + __expf(-g0)) * ua.x * inv;
            vals[4 * i + 1] = __fdividef(1.0f, 1.0f + __expf(-g1)) * ua.y * inv;
            vals[4 * i + 2] = __fdividef(1.0f, 1.0f + __expf(-g2)) * ub.x * inv;
            vals[4 * i + 3] = __fdividef(1.0f, 1.0f + __expf(-g3)) * ub.y * inv;
        }
    }
    __syncthreads();   // all threads done reading s_q / s_g / s_kv / s_ks

    // ---- stage output + coop store (coalesced) ----
    #pragma unroll
    for (int i = 0; i < 32; i++) s_out[tid * 33 + i] = vals[i];
    __syncthreads();
    {
        float* GA0 = g_GA + (size_t)t0 * 128 + h * 32;
        #pragma unroll
        for (int it = 0; it < 8; it++) {
            int idx = it * 256 + tid;
            int token = idx >> 3, c4 = idx & 7;
            const float* s = s_out + token * 33 + c4 * 4;
            float4 o = make_float4(s[0], s[1], s[2], s[3]);
            *(float4*)(GA0 + (size_t)token * 128 + c4 * 4) = o;
        }
    }
}

// ---------------- launcher ----------------
extern "C" void kernel_launch(void* const* d_in, const int* in_sizes, int n_in,
                              void* d_out, int out_size) {
    const float* z    = (const float*)d_in[0];
    const int*   pm   = (const int*)  d_in[1];
    const float* lnw  = (const float*)d_in[2];
    const float* lnb  = (const float*)d_in[3];
    const float* qw   = (const float*)d_in[4];
    const float* qb   = (const float*)d_in[5];
    const float* kw   = (const float*)d_in[6];
    const float* kb   = (const float*)d_in[7];
    const float* vw   = (const float*)d_in[8];
    const float* vb   = (const float*)d_in[9];
    const float* qfw  = (const float*)d_in[10];
    const float* qfb  = (const float*)d_in[11];
    const float* kfw  = (const float*)d_in[12];
    const float* kfb  = (const float*)d_in[13];
    const float* gw   = (const float*)d_in[14];
    const float* gb   = (const float*)d_in[15];
    const float* ow   = (const float*)d_in[16];
    const float* ob   = (const float*)d_in[17];
    float* out = (float*)d_out;

    static int attr_set = 0;
    if (!attr_set) {
        cudaFuncSetAttribute(attn_kernel, cudaFuncAttributeMaxDynamicSharedMemorySize, 107648);
        cudaFuncSetAttribute(mma_gemm<1>, cudaFuncAttributeMaxDynamicSharedMemorySize, 104448);
        cudaFuncSetAttribute(mma_gemm<2>, cudaFuncAttributeMaxDynamicSharedMemorySize, 104448);
        attr_set = 1;
    }

    pack_kernel<<<320, 256>>>(qw, kw, vw, gw, qb, kb, vb, gb, ow);
    ln_kernel<<<8192, 256>>>(z, lnw, lnb);
    mma_gemm<1><<<dim3(1024, 4), 256, 104448>>>(nullptr, nullptr, nullptr);
    attn_kernel<<<dim3(256, 4), 256, 107648>>>(pm, qfw, qfb, kfw, kfb);
    mma_gemm<2><<<dim3(1024, 1), 256, 104448>>>(ob, pm, out);
}